// round 5
// baseline (speedup 1.0000x reference)
#include <cuda_runtime.h>
#include <math.h>

#define NB 8192
#define NV 101
#define NT 30
#define NC 4
#define ND 64
#define NH 128

// Scratch (static device arrays: allowed; no cudaMalloc anywhere)
__device__ float g_h[(size_t)NB * NV * ND];   // final hidden states (B, V*64)
__device__ float g_y[(size_t)NB * NH];        // relu(flat @ Wf1 + bf1)

// ---------------- SMEM layout (floats) ----------------
#define OFF_W2   0          // 64*64   = 4096
#define OFF_WZ   4096       // 132*64  = 8448
#define OFF_WR   12544      // 8448
#define OFF_WW   20992      // 8448
#define OFF_W1   29440      // 4*64    = 256
#define OFF_H    29696      // 101*64  = 6464
#define OFF_WK   36160      // 101*64  = 6464
#define OFF_DYN  42624      // 101*101 = 10201 (pad to 10204)
#define OFF_XT   52828      // 101*4   = 404 (16B aligned)
#define OFF_AGG  53232      // 404
#define OFF_B1   53636
#define OFF_B2   53700
#define OFF_BZ   53764
#define OFF_BR   53828
#define OFF_BW   53892
#define SMEM_FLOATS 53956
#define SMEM_BYTES (SMEM_FLOATS * 4)

__device__ __forceinline__ float sigm(float v) {
    return 1.0f / (1.0f + expf(-v));
}

// acc[2][8] += act[ucX][k] * W[k][d0..d0+7], W row stride fixed at 64 floats
__device__ __forceinline__ void acc_seg(float acc[2][8],
                                        const float* __restrict__ act, int actStride,
                                        const float* __restrict__ W, int K,
                                        int uc0, int uc1, int d0)
{
    const float* a0p = act + uc0 * actStride;
    const float* a1p = act + uc1 * actStride;
    const float* wp  = W + d0;
#pragma unroll 4
    for (int k = 0; k < K; ++k) {
        float a0 = a0p[k];
        float a1 = a1p[k];
        float4 wA = *reinterpret_cast<const float4*>(wp + k * 64);
        float4 wB = *reinterpret_cast<const float4*>(wp + k * 64 + 4);
        acc[0][0] = fmaf(a0, wA.x, acc[0][0]);
        acc[0][1] = fmaf(a0, wA.y, acc[0][1]);
        acc[0][2] = fmaf(a0, wA.z, acc[0][2]);
        acc[0][3] = fmaf(a0, wA.w, acc[0][3]);
        acc[0][4] = fmaf(a0, wB.x, acc[0][4]);
        acc[0][5] = fmaf(a0, wB.y, acc[0][5]);
        acc[0][6] = fmaf(a0, wB.z, acc[0][6]);
        acc[0][7] = fmaf(a0, wB.w, acc[0][7]);
        acc[1][0] = fmaf(a1, wA.x, acc[1][0]);
        acc[1][1] = fmaf(a1, wA.y, acc[1][1]);
        acc[1][2] = fmaf(a1, wA.z, acc[1][2]);
        acc[1][3] = fmaf(a1, wA.w, acc[1][3]);
        acc[1][4] = fmaf(a1, wB.x, acc[1][4]);
        acc[1][5] = fmaf(a1, wB.y, acc[1][5]);
        acc[1][6] = fmaf(a1, wB.z, acc[1][6]);
        acc[1][7] = fmaf(a1, wB.w, acc[1][7]);
    }
}

__global__ __launch_bounds__(512, 1)
void mgcgru_scan(const float* __restrict__ x,
                 const float* __restrict__ dyn,
                 const float* __restrict__ W1, const float* __restrict__ b1,
                 const float* __restrict__ W2, const float* __restrict__ b2,
                 const float* __restrict__ Wz, const float* __restrict__ bz,
                 const float* __restrict__ Wr, const float* __restrict__ br,
                 const float* __restrict__ Ww, const float* __restrict__ bw)
{
    extern __shared__ float sm[];
    float* sW2  = sm + OFF_W2;
    float* sWz  = sm + OFF_WZ;
    float* sWr  = sm + OFF_WR;
    float* sWw  = sm + OFF_WW;
    float* sW1  = sm + OFF_W1;
    float* sh   = sm + OFF_H;
    float* swk  = sm + OFF_WK;
    float* sdyn = sm + OFF_DYN;
    float* sxt  = sm + OFF_XT;
    float* sagg = sm + OFF_AGG;
    float* sb1  = sm + OFF_B1;
    float* sb2  = sm + OFF_B2;
    float* sbz  = sm + OFF_BZ;
    float* sbr  = sm + OFF_BR;
    float* sbw  = sm + OFF_BW;

    const int tid = threadIdx.x;
    const int b   = blockIdx.x;

    for (int i = tid; i < NV * NV; i += 512) sdyn[i] = dyn[i];
    for (int i = tid; i < NC * ND; i += 512) sW1[i] = W1[i];
    for (int i = tid; i < ND * ND; i += 512) sW2[i] = W2[i];
    for (int i = tid; i < 132 * ND; i += 512) {
        sWz[i] = Wz[i]; sWr[i] = Wr[i]; sWw[i] = Ww[i];
    }
    if (tid < ND) {
        sb1[tid] = b1[tid]; sb2[tid] = b2[tid];
        sbz[tid] = bz[tid]; sbr[tid] = br[tid]; sbw[tid] = bw[tid];
    }
    for (int i = tid; i < NV * ND; i += 512) sh[i] = 0.0f;

    // ownership: 51 row-pairs x 8 col-groups = 408 active threads.
    // Threads 408..511 are idle (park at barriers) and burn no FMA issue.
    const int ug = tid >> 3;            // 0..63
    const int dg = tid & 7;             // 0..7
    const bool active = (ug < 51);
    const int u0 = ug * 2;
    const int u1 = u0 + 1;
    const int d0 = dg * 8;
    const int uc0 = (u0 < NV) ? u0 : (NV - 1);
    const int uc1 = (u1 < NV) ? u1 : (NV - 1);
    const bool w0 = active && (u0 < NV);
    const bool w1 = active && (u1 < NV);

    __syncthreads();

    for (int t = 0; t < NT; ++t) {
        // load x_t slice (101 x 4)
        if (tid < NV) {
            float4 xv = *reinterpret_cast<const float4*>(
                x + (((size_t)b * NV + tid) * NT + t) * NC);
            *reinterpret_cast<float4*>(sxt + tid * 4) = xv;
        }
        __syncthreads();

        // stage1: agg[u][c] = sum_v dyn[u][v] * xt[v][c]
        if (tid < NV * NC) {
            int u = tid >> 2, c = tid & 3;
            const float* dr = sdyn + u * NV;
            float s = 0.0f;
#pragma unroll 4
            for (int v = 0; v < NV; ++v) s = fmaf(dr[v], sxt[v * 4 + c], s);
            sagg[tid] = s;
        }
        __syncthreads();

        // stage2: f1 = tanh(agg @ W1 + b1) -> swk
        if (active) {
            float acc[2][8];
#pragma unroll
            for (int j = 0; j < 8; ++j) { float bb = sb1[d0 + j]; acc[0][j] = bb; acc[1][j] = bb; }
            acc_seg(acc, sagg, 4, sW1, 4, uc0, uc1, d0);
            if (w0) {
#pragma unroll
                for (int j = 0; j < 8; ++j) swk[u0 * 64 + d0 + j] = tanhf(acc[0][j]);
            }
            if (w1) {
#pragma unroll
                for (int j = 0; j < 8; ++j) swk[u1 * 64 + d0 + j] = tanhf(acc[1][j]);
            }
        }
        __syncthreads();

        // stage3: agg2 = dyn @ f1 (accumulate in regs, then overwrite swk)
        {
            float acc[2][8];
#pragma unroll
            for (int j = 0; j < 8; ++j) { acc[0][j] = 0.0f; acc[1][j] = 0.0f; }
            if (active) acc_seg(acc, sdyn, NV, swk, NV, uc0, uc1, d0);
            __syncthreads();   // all reads of f1 complete
            if (w0) {
#pragma unroll
                for (int j = 0; j < 8; ++j) swk[u0 * 64 + d0 + j] = acc[0][j];
            }
            if (w1) {
#pragma unroll
                for (int j = 0; j < 8; ++j) swk[u1 * 64 + d0 + j] = acc[1][j];
            }
        }
        __syncthreads();

        // stage4: f = tanh(agg2 @ W2 + b2) -> swk (reg-staged overwrite)
        {
            float acc[2][8];
            if (active) {
#pragma unroll
                for (int j = 0; j < 8; ++j) { float bb = sb2[d0 + j]; acc[0][j] = bb; acc[1][j] = bb; }
                acc_seg(acc, swk, 64, sW2, 64, uc0, uc1, d0);
            }
            __syncthreads();   // all reads of agg2 complete
            if (w0) {
#pragma unroll
                for (int j = 0; j < 8; ++j) swk[u0 * 64 + d0 + j] = tanhf(acc[0][j]);
            }
            if (w1) {
#pragma unroll
                for (int j = 0; j < 8; ++j) swk[u1 * 64 + d0 + j] = tanhf(acc[1][j]);
            }
        }
        __syncthreads();

        // gates. cat = [xt(4) | f(64) | h(64)]
        float zacc[2][8];
        float racc[2][8];   // becomes r*h
        float wacc[2][8];   // candidate pre-activation, x+f part
        if (active) {
#pragma unroll
            for (int j = 0; j < 8; ++j) { float bb = sbz[d0 + j]; zacc[0][j] = bb; zacc[1][j] = bb; }
            acc_seg(zacc, sxt, 4,  sWz,           4,  uc0, uc1, d0);
            acc_seg(zacc, swk, 64, sWz + 4 * 64,  64, uc0, uc1, d0);
            acc_seg(zacc, sh,  64, sWz + 68 * 64, 64, uc0, uc1, d0);
#pragma unroll
            for (int j = 0; j < 8; ++j) { zacc[0][j] = sigm(zacc[0][j]); zacc[1][j] = sigm(zacc[1][j]); }

#pragma unroll
            for (int j = 0; j < 8; ++j) { float bb = sbr[d0 + j]; racc[0][j] = bb; racc[1][j] = bb; }
            acc_seg(racc, sxt, 4,  sWr,           4,  uc0, uc1, d0);
            acc_seg(racc, swk, 64, sWr + 4 * 64,  64, uc0, uc1, d0);
            acc_seg(racc, sh,  64, sWr + 68 * 64, 64, uc0, uc1, d0);
#pragma unroll
            for (int j = 0; j < 8; ++j) {
                racc[0][j] = sigm(racc[0][j]) * sh[uc0 * 64 + d0 + j];
                racc[1][j] = sigm(racc[1][j]) * sh[uc1 * 64 + d0 + j];
            }

#pragma unroll
            for (int j = 0; j < 8; ++j) { float bb = sbw[d0 + j]; wacc[0][j] = bb; wacc[1][j] = bb; }
            acc_seg(wacc, sxt, 4,  sWw,          4,  uc0, uc1, d0);
            acc_seg(wacc, swk, 64, sWw + 4 * 64, 64, uc0, uc1, d0);
        }
        __syncthreads();   // all reads of f and h (by other threads) complete
        // write r*h over swk
        if (w0) {
#pragma unroll
            for (int j = 0; j < 8; ++j) swk[u0 * 64 + d0 + j] = racc[0][j];
        }
        if (w1) {
#pragma unroll
            for (int j = 0; j < 8; ++j) swk[u1 * 64 + d0 + j] = racc[1][j];
        }
        __syncthreads();

        // stage7: wpre += (r*h) @ Ww_h ; h = h + z*(tanh(wpre) - h)
        if (active) {
            acc_seg(wacc, swk, 64, sWw + 68 * 64, 64, uc0, uc1, d0);
            if (w0) {
#pragma unroll
                for (int j = 0; j < 8; ++j) {
                    float cn = tanhf(wacc[0][j]);
                    float hv = sh[u0 * 64 + d0 + j];
                    sh[u0 * 64 + d0 + j] = hv + zacc[0][j] * (cn - hv);
                }
            }
            if (w1) {
#pragma unroll
                for (int j = 0; j < 8; ++j) {
                    float cn = tanhf(wacc[1][j]);
                    float hv = sh[u1 * 64 + d0 + j];
                    sh[u1 * 64 + d0 + j] = hv + zacc[1][j] * (cn - hv);
                }
            }
        }
        // top-of-loop barrier (after x load) orders h writes vs next reads
    }

    __syncthreads();
    for (int i = tid; i < NV * ND; i += 512)
        g_h[(size_t)b * (NV * ND) + i] = sh[i];
}

// ---------------- FC1: g_y = relu(g_h @ Wf1 + bf1), M=8192 K=6464 N=128 ----
__global__ __launch_bounds__(256, 2)
void fc1_kernel(const float* __restrict__ Wf1, const float* __restrict__ bf1)
{
    __shared__ float sA[64 * 16];
    __shared__ float sB[16 * 128];
    const int tid = threadIdx.x;
    const int m0  = blockIdx.x * 64;
    const int tn  = tid & 31;   // 0..31 -> 4 cols each
    const int tm  = tid >> 5;   // 0..7  -> 8 rows each

    float acc[8][4];
#pragma unroll
    for (int i = 0; i < 8; ++i)
#pragma unroll
        for (int j = 0; j < 4; ++j) acc[i][j] = 0.0f;

    const int ai = tid >> 2, ak = (tid & 3) * 4;
    const int bk = tid >> 4, bn = (tid & 15) * 8;

    for (int k0 = 0; k0 < NV * ND; k0 += 16) {
        *reinterpret_cast<float4*>(&sA[ai * 16 + ak]) =
            *reinterpret_cast<const float4*>(&g_h[(size_t)(m0 + ai) * (NV * ND) + k0 + ak]);
        *reinterpret_cast<float4*>(&sB[bk * 128 + bn]) =
            *reinterpret_cast<const float4*>(&Wf1[(size_t)(k0 + bk) * 128 + bn]);
        *reinterpret_cast<float4*>(&sB[bk * 128 + bn + 4]) =
            *reinterpret_cast<const float4*>(&Wf1[(size_t)(k0 + bk) * 128 + bn + 4]);
        __syncthreads();
#pragma unroll
        for (int kk = 0; kk < 16; ++kk) {
            float bv[4];
            *reinterpret_cast<float4*>(bv) =
                *reinterpret_cast<const float4*>(&sB[kk * 128 + tn * 4]);
#pragma unroll
            for (int i = 0; i < 8; ++i) {
                float av = sA[(tm * 8 + i) * 16 + kk];
                acc[i][0] = fmaf(av, bv[0], acc[i][0]);
                acc[i][1] = fmaf(av, bv[1], acc[i][1]);
                acc[i][2] = fmaf(av, bv[2], acc[i][2]);
                acc[i][3] = fmaf(av, bv[3], acc[i][3]);
            }
        }
        __syncthreads();
    }
#pragma unroll
    for (int i = 0; i < 8; ++i) {
        int m = m0 + tm * 8 + i;
#pragma unroll
        for (int j = 0; j < 4; ++j) {
            int n = tn * 4 + j;
            g_y[(size_t)m * 128 + n] = fmaxf(acc[i][j] + bf1[n], 0.0f);
        }
    }
}

// ---------------- head: out = softmax(g_y @ Wf2 + bf2) ----------------
__global__ __launch_bounds__(128)
void head_kernel(const float* __restrict__ Wf2, const float* __restrict__ bf2,
                 float* __restrict__ out)
{
    const int b = blockIdx.x, tid = threadIdx.x;
    __shared__ float sy[128];
    __shared__ float red[128];

    sy[tid] = g_y[(size_t)b * 128 + tid];
    __syncthreads();

    float logit = -3.0e38f;
    if (tid < NV) {
        float s = bf2[tid];
#pragma unroll 4
        for (int k = 0; k < 128; ++k) s = fmaf(sy[k], Wf2[k * NV + tid], s);
        logit = s;
    }
    red[tid] = logit;
    __syncthreads();
#pragma unroll
    for (int off = 64; off > 0; off >>= 1) {
        if (tid < off) red[tid] = fmaxf(red[tid], red[tid + off]);
        __syncthreads();
    }
    float m = red[0];
    __syncthreads();
    float e = (tid < NV) ? expf(logit - m) : 0.0f;
    red[tid] = e;
    __syncthreads();
#pragma unroll
    for (int off = 64; off > 0; off >>= 1) {
        if (tid < off) red[tid] += red[tid + off];
        __syncthreads();
    }
    float s = red[0];
    if (tid < NV) out[(size_t)b * NV + tid] = e / s;
}

extern "C" void kernel_launch(void* const* d_in, const int* in_sizes, int n_in,
                              void* d_out, int out_size)
{
    (void)in_sizes; (void)n_in; (void)out_size;
    const float* x   = (const float*)d_in[0];
    const float* dyn = (const float*)d_in[1];
    const float* W1  = (const float*)d_in[2];
    const float* b1  = (const float*)d_in[3];
    const float* W2  = (const float*)d_in[4];
    const float* b2  = (const float*)d_in[5];
    const float* Wz  = (const float*)d_in[6];
    const float* bz  = (const float*)d_in[7];
    const float* Wr  = (const float*)d_in[8];
    const float* br  = (const float*)d_in[9];
    const float* Ww  = (const float*)d_in[10];
    const float* bw  = (const float*)d_in[11];
    const float* Wf1 = (const float*)d_in[12];
    const float* bf1 = (const float*)d_in[13];
    const float* Wf2 = (const float*)d_in[14];
    const float* bf2 = (const float*)d_in[15];
    float* out = (float*)d_out;

    cudaFuncSetAttribute(mgcgru_scan, cudaFuncAttributeMaxDynamicSharedMemorySize, SMEM_BYTES);
    mgcgru_scan<<<NB, 512, SMEM_BYTES>>>(x, dyn, W1, b1, W2, b2, Wz, bz, Wr, br, Ww, bw);
    fc1_kernel<<<NB / 64, 256>>>(Wf1, bf1);
    head_kernel<<<NB, 128>>>(Wf2, bf2, out);
}

// round 7
// speedup vs baseline: 1.5829x; 1.5829x over previous
#include <cuda_runtime.h>
#include <math.h>

#define NB 8192
#define NV 101
#define NT 30
#define NC 4
#define ND 64
#define NH 128
#define DSTR 104   // padded dyn row stride (16B-aligned float4 rows)

typedef unsigned long long u64;

// Scratch (static device arrays: allowed; no cudaMalloc anywhere)
__device__ float g_h[(size_t)NB * NV * ND];   // final hidden states (B, V*64)
__device__ float g_y[(size_t)NB * NH];        // relu(flat @ Wf1 + bf1)

// ---------------- SMEM layout (floats) ----------------
#define OFF_W2   0          // 64*64   = 4096
#define OFF_WZ   4096       // 132*64  = 8448
#define OFF_WR   12544      // 8448
#define OFF_WW   20992      // 8448
#define OFF_W1   29440      // 4*64    = 256
#define OFF_H    29696      // 101*64  = 6464
#define OFF_WK   36160      // 101*64  = 6464
#define OFF_DYN  42624      // 101*104 = 10504 (padded rows)
#define OFF_XT   53128      // 101*4   = 404 (pad 408)
#define OFF_AGG  53536      // 404 (pad 408)
#define OFF_B1   53944
#define OFF_B2   54008
#define OFF_BZ   54072
#define OFF_BR   54136
#define OFF_BW   54200
#define SMEM_FLOATS 54264
#define SMEM_BYTES (SMEM_FLOATS * 4)   // 217,056 B < 227 KB cap

__device__ __forceinline__ float sigm(float v) {
    return 1.0f / (1.0f + expf(-v));
}

// ---- packed f32x2 primitives (exact fp32 RN, 2 FMAs/instr) ----
__device__ __forceinline__ u64 pk2(float lo, float hi) {
    u64 r; asm("mov.b64 %0, {%1, %2};" : "=l"(r) : "f"(lo), "f"(hi)); return r;
}
__device__ __forceinline__ void upk2(float& lo, float& hi, u64 v) {
    asm("mov.b64 {%0, %1}, %2;" : "=f"(lo), "=f"(hi) : "l"(v));
}
__device__ __forceinline__ u64 ffma2(u64 a, u64 b, u64 c) {
    u64 d; asm("fma.rn.f32x2 %0, %1, %2, %3;" : "=l"(d) : "l"(a), "l"(b), "l"(c));
    return d;
}

__device__ __forceinline__ void fma_row(u64 acc[4], u64 aa, u64 w0, u64 w1, u64 w2, u64 w3) {
    acc[0] = ffma2(aa, w0, acc[0]);
    acc[1] = ffma2(aa, w1, acc[1]);
    acc[2] = ffma2(aa, w2, acc[2]);
    acc[3] = ffma2(aa, w3, acc[3]);
}

// acc[4 rows][4 col-pairs] += act_rows(k) * W[k][d0..d0+7]; W row stride 64.
// K multiple of 4; act row pointers 16B-aligned, k-contiguous.
__device__ __forceinline__ void gemm4(u64 acc[4][4],
    const float* __restrict__ a0, const float* __restrict__ a1,
    const float* __restrict__ a2, const float* __restrict__ a3,
    const float* __restrict__ W, int K, int d0)
{
    const float* wr = W + d0;
#pragma unroll 2
    for (int k = 0; k < K; k += 4) {
        float4 v0 = *reinterpret_cast<const float4*>(a0 + k);
        float4 v1 = *reinterpret_cast<const float4*>(a1 + k);
        float4 v2 = *reinterpret_cast<const float4*>(a2 + k);
        float4 v3 = *reinterpret_cast<const float4*>(a3 + k);
#pragma unroll
        for (int kk = 0; kk < 4; ++kk) {
            const float* wp = wr + (k + kk) * 64;
            ulonglong2 wa = *reinterpret_cast<const ulonglong2*>(wp);
            ulonglong2 wb = *reinterpret_cast<const ulonglong2*>(wp + 4);
            float f0 = (reinterpret_cast<const float*>(&v0))[kk];
            float f1 = (reinterpret_cast<const float*>(&v1))[kk];
            float f2 = (reinterpret_cast<const float*>(&v2))[kk];
            float f3 = (reinterpret_cast<const float*>(&v3))[kk];
            fma_row(acc[0], pk2(f0, f0), wa.x, wa.y, wb.x, wb.y);
            fma_row(acc[1], pk2(f1, f1), wa.x, wa.y, wb.x, wb.y);
            fma_row(acc[2], pk2(f2, f2), wa.x, wa.y, wb.x, wb.y);
            fma_row(acc[3], pk2(f3, f3), wa.x, wa.y, wb.x, wb.y);
        }
    }
}

// single-k tail step
__device__ __forceinline__ void gemm1(u64 acc[4][4],
    float a0, float a1, float a2, float a3,
    const float* __restrict__ Wrow, int d0)
{
    ulonglong2 wa = *reinterpret_cast<const ulonglong2*>(Wrow + d0);
    ulonglong2 wb = *reinterpret_cast<const ulonglong2*>(Wrow + d0 + 4);
    fma_row(acc[0], pk2(a0, a0), wa.x, wa.y, wb.x, wb.y);
    fma_row(acc[1], pk2(a1, a1), wa.x, wa.y, wb.x, wb.y);
    fma_row(acc[2], pk2(a2, a2), wa.x, wa.y, wb.x, wb.y);
    fma_row(acc[3], pk2(a3, a3), wa.x, wa.y, wb.x, wb.y);
}

__device__ __forceinline__ void bias_init(u64 acc[4][4], const float* bb, int d0) {
    u64 t0 = pk2(bb[d0],     bb[d0 + 1]);
    u64 t1 = pk2(bb[d0 + 2], bb[d0 + 3]);
    u64 t2 = pk2(bb[d0 + 4], bb[d0 + 5]);
    u64 t3 = pk2(bb[d0 + 6], bb[d0 + 7]);
#pragma unroll
    for (int r = 0; r < 4; ++r) { acc[r][0] = t0; acc[r][1] = t1; acc[r][2] = t2; acc[r][3] = t3; }
}

__device__ __forceinline__ void zero_init(u64 acc[4][4]) {
    u64 z = pk2(0.0f, 0.0f);
#pragma unroll
    for (int r = 0; r < 4; ++r) { acc[r][0] = z; acc[r][1] = z; acc[r][2] = z; acc[r][3] = z; }
}

__device__ __forceinline__ void unpack8(float o[8], const u64 acc[4]) {
    upk2(o[0], o[1], acc[0]); upk2(o[2], o[3], acc[1]);
    upk2(o[4], o[5], acc[2]); upk2(o[6], o[7], acc[3]);
}

__device__ __forceinline__ void store_row_raw(float* dst, const u64 acc[4]) {
    float o[8]; unpack8(o, acc);
    *reinterpret_cast<float4*>(dst)     = make_float4(o[0], o[1], o[2], o[3]);
    *reinterpret_cast<float4*>(dst + 4) = make_float4(o[4], o[5], o[6], o[7]);
}

__device__ __forceinline__ void store_row_tanh(float* dst, const u64 acc[4]) {
    float o[8]; unpack8(o, acc);
    *reinterpret_cast<float4*>(dst)     = make_float4(tanhf(o[0]), tanhf(o[1]), tanhf(o[2]), tanhf(o[3]));
    *reinterpret_cast<float4*>(dst + 4) = make_float4(tanhf(o[4]), tanhf(o[5]), tanhf(o[6]), tanhf(o[7]));
}

__global__ __launch_bounds__(256, 1)
void mgcgru_scan(const float* __restrict__ x,
                 const float* __restrict__ dyn,
                 const float* __restrict__ W1, const float* __restrict__ b1,
                 const float* __restrict__ W2, const float* __restrict__ b2,
                 const float* __restrict__ Wz, const float* __restrict__ bz,
                 const float* __restrict__ Wr, const float* __restrict__ br,
                 const float* __restrict__ Ww, const float* __restrict__ bw)
{
    extern __shared__ float sm[];
    float* sW2  = sm + OFF_W2;
    float* sWz  = sm + OFF_WZ;
    float* sWr  = sm + OFF_WR;
    float* sWw  = sm + OFF_WW;
    float* sW1  = sm + OFF_W1;
    float* sh   = sm + OFF_H;
    float* swk  = sm + OFF_WK;
    float* sdyn = sm + OFF_DYN;
    float* sxt  = sm + OFF_XT;
    float* sagg = sm + OFF_AGG;
    float* sb1  = sm + OFF_B1;
    float* sb2  = sm + OFF_B2;
    float* sbz  = sm + OFF_BZ;
    float* sbr  = sm + OFF_BR;
    float* sbw  = sm + OFF_BW;

    const int tid = threadIdx.x;
    const int b   = blockIdx.x;

    // preload weights (dyn rows padded to stride 104)
    for (int i = tid; i < NV * DSTR; i += 256) {
        int u = i / DSTR, v = i - u * DSTR;
        sdyn[i] = (v < NV) ? dyn[u * NV + v] : 0.0f;
    }
    for (int i = tid; i < NC * ND; i += 256) sW1[i] = W1[i];
    for (int i = tid; i < ND * ND; i += 256) sW2[i] = W2[i];
    for (int i = tid; i < 132 * ND; i += 256) {
        sWz[i] = Wz[i]; sWr[i] = Wr[i]; sWw[i] = Ww[i];
    }
    if (tid < ND) {
        sb1[tid] = b1[tid]; sb2[tid] = b2[tid];
        sbz[tid] = bz[tid]; sbr[tid] = br[tid]; sbw[tid] = bw[tid];
    }
    for (int i = tid; i < NV * ND; i += 256) sh[i] = 0.0f;

    // ownership: 26 row-groups (4 rows each) x 8 col-groups = 208 active threads
    const int ug = tid >> 3;            // 0..31
    const int dg = tid & 7;             // 0..7
    const bool active = (ug < 26);
    const int d0 = dg * 8;
    int u_[4], uc[4]; bool wr_[4];
#pragma unroll
    for (int r = 0; r < 4; ++r) {
        u_[r] = ug * 4 + r;
        uc[r] = (u_[r] < NV) ? u_[r] : (NV - 1);
        wr_[r] = active && (u_[r] < NV);
    }

    __syncthreads();

    for (int t = 0; t < NT; ++t) {
        // load x_t slice (101 x 4)
        if (tid < NV) {
            float4 xv = *reinterpret_cast<const float4*>(
                x + (((size_t)b * NV + tid) * NT + t) * NC);
            *reinterpret_cast<float4*>(sxt + tid * 4) = xv;
        }
        __syncthreads();

        // stage1: agg[u][c] = sum_v dyn[u][v] * xt[v][c]  (tiny: 41k FMA)
        for (int i = tid; i < NV * NC; i += 256) {
            int uu = i >> 2, c = i & 3;
            const float* dr = sdyn + uu * DSTR;
            float s = 0.0f;
#pragma unroll 4
            for (int v = 0; v < NV; ++v) s = fmaf(dr[v], sxt[v * 4 + c], s);
            sagg[i] = s;
        }
        __syncthreads();

        // stage2: f1 = tanh(agg @ W1 + b1) -> swk
        if (active) {
            u64 acc[4][4];
            bias_init(acc, sb1, d0);
            gemm4(acc, sagg + uc[0] * 4, sagg + uc[1] * 4,
                       sagg + uc[2] * 4, sagg + uc[3] * 4, sW1, 4, d0);
#pragma unroll
            for (int r = 0; r < 4; ++r)
                if (wr_[r]) store_row_tanh(swk + u_[r] * 64 + d0, acc[r]);
        }
        __syncthreads();

        // stage3: agg2 = dyn @ f1 (reg-staged overwrite of swk)
        {
            u64 acc[4][4];
            if (active) {
                zero_init(acc);
                gemm4(acc, sdyn + uc[0] * DSTR, sdyn + uc[1] * DSTR,
                           sdyn + uc[2] * DSTR, sdyn + uc[3] * DSTR, swk, 100, d0);
                gemm1(acc, sdyn[uc[0] * DSTR + 100], sdyn[uc[1] * DSTR + 100],
                           sdyn[uc[2] * DSTR + 100], sdyn[uc[3] * DSTR + 100],
                           swk + 100 * 64, d0);
            }
            __syncthreads();   // all reads of f1 complete
#pragma unroll
            for (int r = 0; r < 4; ++r)
                if (wr_[r]) store_row_raw(swk + u_[r] * 64 + d0, acc[r]);
        }
        __syncthreads();

        // stage4: f = tanh(agg2 @ W2 + b2) -> swk (reg-staged overwrite)
        {
            u64 acc[4][4];
            if (active) {
                bias_init(acc, sb2, d0);
                gemm4(acc, swk + uc[0] * 64, swk + uc[1] * 64,
                           swk + uc[2] * 64, swk + uc[3] * 64, sW2, 64, d0);
            }
            __syncthreads();   // all reads of agg2 complete
#pragma unroll
            for (int r = 0; r < 4; ++r)
                if (wr_[r]) store_row_tanh(swk + u_[r] * 64 + d0, acc[r]);
        }
        __syncthreads();

        // gates. cat = [xt(4) | f(64) | h(64)]
        float zf[4][8];
        float rhf[4][8];
        u64 wacc[4][4];
        if (active) {
            {
                u64 acc[4][4];
                bias_init(acc, sbz, d0);
                gemm4(acc, sxt + uc[0] * 4, sxt + uc[1] * 4,
                           sxt + uc[2] * 4, sxt + uc[3] * 4, sWz, 4, d0);
                gemm4(acc, swk + uc[0] * 64, swk + uc[1] * 64,
                           swk + uc[2] * 64, swk + uc[3] * 64, sWz + 4 * 64, 64, d0);
                gemm4(acc, sh + uc[0] * 64, sh + uc[1] * 64,
                           sh + uc[2] * 64, sh + uc[3] * 64, sWz + 68 * 64, 64, d0);
#pragma unroll
                for (int r = 0; r < 4; ++r) {
                    unpack8(zf[r], acc[r]);
#pragma unroll
                    for (int j = 0; j < 8; ++j) zf[r][j] = sigm(zf[r][j]);
                }
            }
            {
                u64 acc[4][4];
                bias_init(acc, sbr, d0);
                gemm4(acc, sxt + uc[0] * 4, sxt + uc[1] * 4,
                           sxt + uc[2] * 4, sxt + uc[3] * 4, sWr, 4, d0);
                gemm4(acc, swk + uc[0] * 64, swk + uc[1] * 64,
                           swk + uc[2] * 64, swk + uc[3] * 64, sWr + 4 * 64, 64, d0);
                gemm4(acc, sh + uc[0] * 64, sh + uc[1] * 64,
                           sh + uc[2] * 64, sh + uc[3] * 64, sWr + 68 * 64, 64, d0);
#pragma unroll
                for (int r = 0; r < 4; ++r) {
                    unpack8(rhf[r], acc[r]);
                    float4 h0 = *reinterpret_cast<const float4*>(sh + uc[r] * 64 + d0);
                    float4 h1 = *reinterpret_cast<const float4*>(sh + uc[r] * 64 + d0 + 4);
                    rhf[r][0] = sigm(rhf[r][0]) * h0.x;
                    rhf[r][1] = sigm(rhf[r][1]) * h0.y;
                    rhf[r][2] = sigm(rhf[r][2]) * h0.z;
                    rhf[r][3] = sigm(rhf[r][3]) * h0.w;
                    rhf[r][4] = sigm(rhf[r][4]) * h1.x;
                    rhf[r][5] = sigm(rhf[r][5]) * h1.y;
                    rhf[r][6] = sigm(rhf[r][6]) * h1.z;
                    rhf[r][7] = sigm(rhf[r][7]) * h1.w;
                }
            }
            bias_init(wacc, sbw, d0);
            gemm4(wacc, sxt + uc[0] * 4, sxt + uc[1] * 4,
                        sxt + uc[2] * 4, sxt + uc[3] * 4, sWw, 4, d0);
            gemm4(wacc, swk + uc[0] * 64, swk + uc[1] * 64,
                        swk + uc[2] * 64, swk + uc[3] * 64, sWw + 4 * 64, 64, d0);
        }
        __syncthreads();   // all reads of f and h (by other threads) complete
        // write r*h over swk
#pragma unroll
        for (int r = 0; r < 4; ++r) {
            if (wr_[r]) {
                *reinterpret_cast<float4*>(swk + u_[r] * 64 + d0) =
                    make_float4(rhf[r][0], rhf[r][1], rhf[r][2], rhf[r][3]);
                *reinterpret_cast<float4*>(swk + u_[r] * 64 + d0 + 4) =
                    make_float4(rhf[r][4], rhf[r][5], rhf[r][6], rhf[r][7]);
            }
        }
        __syncthreads();

        // stage7: wpre += (r*h) @ Ww_h ; h = h + z*(tanh(wpre) - h)
        if (active) {
            gemm4(wacc, swk + uc[0] * 64, swk + uc[1] * 64,
                        swk + uc[2] * 64, swk + uc[3] * 64, sWw + 68 * 64, 64, d0);
#pragma unroll
            for (int r = 0; r < 4; ++r) {
                if (wr_[r]) {
                    float o[8]; unpack8(o, wacc[r]);
                    float* hp = sh + u_[r] * 64 + d0;
                    float4 h0 = *reinterpret_cast<const float4*>(hp);
                    float4 h1 = *reinterpret_cast<const float4*>(hp + 4);
                    float hv[8] = {h0.x, h0.y, h0.z, h0.w, h1.x, h1.y, h1.z, h1.w};
                    float hn[8];
#pragma unroll
                    for (int j = 0; j < 8; ++j) {
                        float cn = tanhf(o[j]);
                        hn[j] = hv[j] + zf[r][j] * (cn - hv[j]);
                    }
                    *reinterpret_cast<float4*>(hp)     = make_float4(hn[0], hn[1], hn[2], hn[3]);
                    *reinterpret_cast<float4*>(hp + 4) = make_float4(hn[4], hn[5], hn[6], hn[7]);
                }
            }
        }
        // top-of-loop barrier (after x load) orders h writes vs next reads
    }

    __syncthreads();
    for (int i = tid; i < NV * ND; i += 256)
        g_h[(size_t)b * (NV * ND) + i] = sh[i];
}

// ---------------- FC1: g_y = relu(g_h @ Wf1 + bf1), M=8192 K=6464 N=128 ----
__global__ __launch_bounds__(256, 2)
void fc1_kernel(const float* __restrict__ Wf1, const float* __restrict__ bf1)
{
    __shared__ float sA[64 * 16];
    __shared__ float sB[16 * 128];
    const int tid = threadIdx.x;
    const int m0  = blockIdx.x * 64;
    const int tn  = tid & 31;   // 0..31 -> 4 cols each
    const int tm  = tid >> 5;   // 0..7  -> 8 rows each

    float acc[8][4];
#pragma unroll
    for (int i = 0; i < 8; ++i)
#pragma unroll
        for (int j = 0; j < 4; ++j) acc[i][j] = 0.0f;

    const int ai = tid >> 2, ak = (tid & 3) * 4;
    const int bk = tid >> 4, bn = (tid & 15) * 8;

    for (int k0 = 0; k0 < NV * ND; k0 += 16) {
        *reinterpret_cast<float4*>(&sA[ai * 16 + ak]) =
            *reinterpret_cast<const float4*>(&g_h[(size_t)(m0 + ai) * (NV * ND) + k0 + ak]);
        *reinterpret_cast<float4*>(&sB[bk * 128 + bn]) =
            *reinterpret_cast<const float4*>(&Wf1[(size_t)(k0 + bk) * 128 + bn]);
        *reinterpret_cast<float4*>(&sB[bk * 128 + bn + 4]) =
            *reinterpret_cast<const float4*>(&Wf1[(size_t)(k0 + bk) * 128 + bn + 4]);
        __syncthreads();
#pragma unroll
        for (int kk = 0; kk < 16; ++kk) {
            float bv[4];
            *reinterpret_cast<float4*>(bv) =
                *reinterpret_cast<const float4*>(&sB[kk * 128 + tn * 4]);
#pragma unroll
            for (int i = 0; i < 8; ++i) {
                float av = sA[(tm * 8 + i) * 16 + kk];
                acc[i][0] = fmaf(av, bv[0], acc[i][0]);
                acc[i][1] = fmaf(av, bv[1], acc[i][1]);
                acc[i][2] = fmaf(av, bv[2], acc[i][2]);
                acc[i][3] = fmaf(av, bv[3], acc[i][3]);
            }
        }
        __syncthreads();
    }
#pragma unroll
    for (int i = 0; i < 8; ++i) {
        int m = m0 + tm * 8 + i;
#pragma unroll
        for (int j = 0; j < 4; ++j) {
            int n = tn * 4 + j;
            g_y[(size_t)m * 128 + n] = fmaxf(acc[i][j] + bf1[n], 0.0f);
        }
    }
}

// ---------------- head: out = softmax(g_y @ Wf2 + bf2) ----------------
__global__ __launch_bounds__(128)
void head_kernel(const float* __restrict__ Wf2, const float* __restrict__ bf2,
                 float* __restrict__ out)
{
    const int b = blockIdx.x, tid = threadIdx.x;
    __shared__ float sy[128];
    __shared__ float red[128];

    sy[tid] = g_y[(size_t)b * 128 + tid];
    __syncthreads();

    float logit = -3.0e38f;
    if (tid < NV) {
        float s = bf2[tid];
#pragma unroll 4
        for (int k = 0; k < 128; ++k) s = fmaf(sy[k], Wf2[k * NV + tid], s);
        logit = s;
    }
    red[tid] = logit;
    __syncthreads();
#pragma unroll
    for (int off = 64; off > 0; off >>= 1) {
        if (tid < off) red[tid] = fmaxf(red[tid], red[tid + off]);
        __syncthreads();
    }
    float m = red[0];
    __syncthreads();
    float e = (tid < NV) ? expf(logit - m) : 0.0f;
    red[tid] = e;
    __syncthreads();
#pragma unroll
    for (int off = 64; off > 0; off >>= 1) {
        if (tid < off) red[tid] += red[tid + off];
        __syncthreads();
    }
    float s = red[0];
    if (tid < NV) out[(size_t)b * NV + tid] = e / s;
}

extern "C" void kernel_launch(void* const* d_in, const int* in_sizes, int n_in,
                              void* d_out, int out_size)
{
    (void)in_sizes; (void)n_in; (void)out_size;
    const float* x   = (const float*)d_in[0];
    const float* dyn = (const float*)d_in[1];
    const float* W1  = (const float*)d_in[2];
    const float* b1  = (const float*)d_in[3];
    const float* W2  = (const float*)d_in[4];
    const float* b2  = (const float*)d_in[5];
    const float* Wz  = (const float*)d_in[6];
    const float* bz  = (const float*)d_in[7];
    const float* Wr  = (const float*)d_in[8];
    const float* br  = (const float*)d_in[9];
    const float* Ww  = (const float*)d_in[10];
    const float* bw  = (const float*)d_in[11];
    const float* Wf1 = (const float*)d_in[12];
    const float* bf1 = (const float*)d_in[13];
    const float* Wf2 = (const float*)d_in[14];
    const float* bf2 = (const float*)d_in[15];
    float* out = (float*)d_out;

    cudaFuncSetAttribute(mgcgru_scan, cudaFuncAttributeMaxDynamicSharedMemorySize, SMEM_BYTES);
    mgcgru_scan<<<NB, 256, SMEM_BYTES>>>(x, dyn, W1, b1, W2, b2, Wz, bz, Wr, br, Ww, bw);
    fc1_kernel<<<NB / 64, 256>>>(Wf1, bf1);
    head_kernel<<<NB, 128>>>(Wf2, bf2, out);
}

// round 8
// speedup vs baseline: 2.3182x; 1.4646x over previous
#include <cuda_runtime.h>
#include <math.h>

#define NB 8192
#define NV 101
#define NT 30
#define NC 4
#define ND 64
#define NH 128
#define NVP 104     // padded row count (zeroed pad rows 101..103)
#define DSTR 104    // padded dyn row stride (16B-aligned float4 rows)

typedef unsigned long long u64;

// Scratch (static device arrays: allowed; no cudaMalloc anywhere)
__device__ float g_h[(size_t)NB * NV * ND];   // final hidden states (B, V*64)
__device__ float g_y[(size_t)NB * NH];        // relu(flat @ Wf1 + bf1)

// ---------------- SMEM layout (floats) ----------------
#define OFF_W2   0          // 64*64    = 4096
#define OFF_WZ   4096       // 132*64   = 8448
#define OFF_WR   12544      // 8448
#define OFF_WW   20992      // 8448
#define OFF_W1   29440      // 4*64     = 256
#define OFF_H    29696      // 104*64   = 6656
#define OFF_WK   36352      // 104*64   = 6656
#define OFF_DYN  43008      // 104*104  = 10816
#define OFF_XT   53824      // 104*4    = 416
#define OFF_AGG  54240      // 416
#define OFF_B1   54656
#define OFF_B2   54720
#define OFF_BZ   54784
#define OFF_BR   54848
#define OFF_BW   54912
#define SMEM_FLOATS 54976
#define SMEM_BYTES (SMEM_FLOATS * 4)   // 219,904 B

__device__ __forceinline__ float sigm(float v) {
    return 1.0f / (1.0f + expf(-v));
}

// ---- packed f32x2 primitives (exact fp32 RN, 2 FMAs/instr) ----
__device__ __forceinline__ u64 pk2(float lo, float hi) {
    u64 r; asm("mov.b64 %0, {%1, %2};" : "=l"(r) : "f"(lo), "f"(hi)); return r;
}
__device__ __forceinline__ void upk2(float& lo, float& hi, u64 v) {
    asm("mov.b64 {%0, %1}, %2;" : "=f"(lo), "=f"(hi) : "l"(v));
}
__device__ __forceinline__ u64 ffma2(u64 a, u64 b, u64 c) {
    u64 d; asm("fma.rn.f32x2 %0, %1, %2, %3;" : "=l"(d) : "l"(a), "l"(b), "l"(c));
    return d;
}

// acc[7 rows][2 u64 = 4 cols] += act[rbase+r][k] * W[k][c0..c0+3]
// W row stride fixed 64 floats. K multiple of 4. All pointers 16B aligned.
// Weight LDS.128 is conflict-free + warp-half broadcast; act loads are
// row-group broadcast float4.
__device__ __forceinline__ void gemmT(u64 acc[7][2],
    const float* __restrict__ act, int stride, int rbase,
    const float* __restrict__ W, int K, int c0)
{
    const float* wp = W + c0;
#pragma unroll 2
    for (int k = 0; k < K; k += 4) {
        float4 av[7];
#pragma unroll
        for (int r = 0; r < 7; ++r)
            av[r] = *reinterpret_cast<const float4*>(act + (rbase + r) * stride + k);
#pragma unroll
        for (int kk = 0; kk < 4; ++kk) {
            ulonglong2 wv = *reinterpret_cast<const ulonglong2*>(wp + (k + kk) * 64);
#pragma unroll
            for (int r = 0; r < 7; ++r) {
                float a = reinterpret_cast<const float*>(&av[r])[kk];
                u64 ad = pk2(a, a);
                acc[r][0] = ffma2(ad, wv.x, acc[r][0]);
                acc[r][1] = ffma2(ad, wv.y, acc[r][1]);
            }
        }
    }
}

__device__ __forceinline__ void bias7(u64 acc[7][2], const float* bb, int c0) {
    u64 t0 = pk2(bb[c0],     bb[c0 + 1]);
    u64 t1 = pk2(bb[c0 + 2], bb[c0 + 3]);
#pragma unroll
    for (int r = 0; r < 7; ++r) { acc[r][0] = t0; acc[r][1] = t1; }
}

__device__ __forceinline__ void zero7(u64 acc[7][2]) {
    u64 z = pk2(0.0f, 0.0f);
#pragma unroll
    for (int r = 0; r < 7; ++r) { acc[r][0] = z; acc[r][1] = z; }
}

__global__ __launch_bounds__(256, 1)
void mgcgru_scan(const float* __restrict__ x,
                 const float* __restrict__ dyn,
                 const float* __restrict__ W1, const float* __restrict__ b1,
                 const float* __restrict__ W2, const float* __restrict__ b2,
                 const float* __restrict__ Wz, const float* __restrict__ bz,
                 const float* __restrict__ Wr, const float* __restrict__ br,
                 const float* __restrict__ Ww, const float* __restrict__ bw)
{
    extern __shared__ float sm[];
    float* sW2  = sm + OFF_W2;
    float* sWz  = sm + OFF_WZ;
    float* sWr  = sm + OFF_WR;
    float* sWw  = sm + OFF_WW;
    float* sW1  = sm + OFF_W1;
    float* sh   = sm + OFF_H;
    float* swk  = sm + OFF_WK;
    float* sdyn = sm + OFF_DYN;
    float* sxt  = sm + OFF_XT;
    float* sagg = sm + OFF_AGG;
    float* sb1  = sm + OFF_B1;
    float* sb2  = sm + OFF_B2;
    float* sbz  = sm + OFF_BZ;
    float* sbr  = sm + OFF_BR;
    float* sbw  = sm + OFF_BW;

    const int tid = threadIdx.x;
    const int b   = blockIdx.x;

    // preload weights; zero-pad dyn rows/cols to 104x104
    for (int i = tid; i < NVP * DSTR; i += 256) {
        int u = i / DSTR, v = i - u * DSTR;
        sdyn[i] = (u < NV && v < NV) ? dyn[u * NV + v] : 0.0f;
    }
    for (int i = tid; i < NC * ND; i += 256) sW1[i] = W1[i];
    for (int i = tid; i < ND * ND; i += 256) sW2[i] = W2[i];
    for (int i = tid; i < 132 * ND; i += 256) {
        sWz[i] = Wz[i]; sWr[i] = Wr[i]; sWw[i] = Ww[i];
    }
    if (tid < ND) {
        sb1[tid] = b1[tid]; sb2[tid] = b2[tid];
        sbz[tid] = bz[tid]; sbr[tid] = br[tid]; sbw[tid] = bw[tid];
    }
    // zero full padded state (pad rows must be 0 and stay 0)
    for (int i = tid; i < NVP * ND; i += 256) { sh[i] = 0.0f; swk[i] = 0.0f; }
    for (int i = tid; i < NVP * NC; i += 256) { sxt[i] = 0.0f; sagg[i] = 0.0f; }

    // ownership: warp w covers rows [w*14, w*14+14); lane half lr gives 7 rows;
    // lane col-group lc gives 4 consecutive cols. 8 warps x 14 = 112 >= 104.
    const int w    = tid >> 5;
    const int lane = tid & 31;
    const int lr   = lane >> 4;        // 0..1
    const int lc   = lane & 15;        // 0..15
    const int c0   = lc * 4;
    const int rbase = w * 14 + lr * 7; // 0,7,14,...,105

    __syncthreads();

    for (int t = 0; t < NT; ++t) {
        // load x_t slice (101 x 4)
        if (tid < NV) {
            float4 xv = *reinterpret_cast<const float4*>(
                x + (((size_t)b * NV + tid) * NT + t) * NC);
            *reinterpret_cast<float4*>(sxt + tid * 4) = xv;
        }
        __syncthreads();

        // stage1: agg[u][c] = sum_v dyn[u][v] * xt[v][c]  (tiny)
        for (int i = tid; i < NV * NC; i += 256) {
            int uu = i >> 2, c = i & 3;
            const float* dr = sdyn + uu * DSTR;
            float s = 0.0f;
#pragma unroll 4
            for (int v = 0; v < NV; ++v) s = fmaf(dr[v], sxt[v * 4 + c], s);
            sagg[i] = s;
        }
        __syncthreads();

        // stage2: f1 = tanh(agg @ W1 + b1) -> swk
        {
            u64 acc[7][2];
            bias7(acc, sb1, c0);
            gemmT(acc, sagg, 4, rbase, sW1, 4, c0);
#pragma unroll
            for (int r = 0; r < 7; ++r) {
                int row = rbase + r;
                if (row < NV) {
                    float o0, o1, o2, o3;
                    upk2(o0, o1, acc[r][0]); upk2(o2, o3, acc[r][1]);
                    *reinterpret_cast<float4*>(swk + row * 64 + c0) =
                        make_float4(tanhf(o0), tanhf(o1), tanhf(o2), tanhf(o3));
                }
            }
        }
        __syncthreads();

        // stage3: agg2 = dyn @ f1 (K padded to 104; pad rows of swk are zero)
        {
            u64 acc[7][2];
            zero7(acc);
            gemmT(acc, sdyn, DSTR, rbase, swk, NVP, c0);
            __syncthreads();   // all reads of f1 complete
#pragma unroll
            for (int r = 0; r < 7; ++r) {
                int row = rbase + r;
                if (row < NV) {
                    float o0, o1, o2, o3;
                    upk2(o0, o1, acc[r][0]); upk2(o2, o3, acc[r][1]);
                    *reinterpret_cast<float4*>(swk + row * 64 + c0) =
                        make_float4(o0, o1, o2, o3);
                }
            }
        }
        __syncthreads();

        // stage4: f = tanh(agg2 @ W2 + b2) -> swk (reg-staged overwrite)
        {
            u64 acc[7][2];
            bias7(acc, sb2, c0);
            gemmT(acc, swk, 64, rbase, sW2, 64, c0);
            __syncthreads();   // all reads of agg2 complete
#pragma unroll
            for (int r = 0; r < 7; ++r) {
                int row = rbase + r;
                if (row < NV) {
                    float o0, o1, o2, o3;
                    upk2(o0, o1, acc[r][0]); upk2(o2, o3, acc[r][1]);
                    *reinterpret_cast<float4*>(swk + row * 64 + c0) =
                        make_float4(tanhf(o0), tanhf(o1), tanhf(o2), tanhf(o3));
                }
            }
        }
        __syncthreads();

        // gates. cat = [xt(4) | f(64) | h(64)]
        float zf[7][4];
        float rh[7][4];
        u64 wacc[7][2];
        {
            u64 acc[7][2];
            bias7(acc, sbz, c0);
            gemmT(acc, sxt, 4,  rbase, sWz,           4,   c0);
            gemmT(acc, swk, 64, rbase, sWz + 4 * 64,  64,  c0);
            gemmT(acc, sh,  64, rbase, sWz + 68 * 64, 64,  c0);
#pragma unroll
            for (int r = 0; r < 7; ++r) {
                upk2(zf[r][0], zf[r][1], acc[r][0]);
                upk2(zf[r][2], zf[r][3], acc[r][1]);
#pragma unroll
                for (int j = 0; j < 4; ++j) zf[r][j] = sigm(zf[r][j]);
            }
        }
        {
            u64 acc[7][2];
            bias7(acc, sbr, c0);
            gemmT(acc, sxt, 4,  rbase, sWr,           4,   c0);
            gemmT(acc, swk, 64, rbase, sWr + 4 * 64,  64,  c0);
            gemmT(acc, sh,  64, rbase, sWr + 68 * 64, 64,  c0);
#pragma unroll
            for (int r = 0; r < 7; ++r) {
                upk2(rh[r][0], rh[r][1], acc[r][0]);
                upk2(rh[r][2], rh[r][3], acc[r][1]);
                float4 hv = *reinterpret_cast<const float4*>(sh + (rbase + r) * 64 + c0);
                rh[r][0] = sigm(rh[r][0]) * hv.x;
                rh[r][1] = sigm(rh[r][1]) * hv.y;
                rh[r][2] = sigm(rh[r][2]) * hv.z;
                rh[r][3] = sigm(rh[r][3]) * hv.w;
            }
        }
        bias7(wacc, sbw, c0);
        gemmT(wacc, sxt, 4,  rbase, sWw,          4,  c0);
        gemmT(wacc, swk, 64, rbase, sWw + 4 * 64, 64, c0);

        __syncthreads();   // all reads of f and h (by other lanes) complete
        // write r*h over swk (pad rows stay zero: guarded)
#pragma unroll
        for (int r = 0; r < 7; ++r) {
            int row = rbase + r;
            if (row < NV)
                *reinterpret_cast<float4*>(swk + row * 64 + c0) =
                    make_float4(rh[r][0], rh[r][1], rh[r][2], rh[r][3]);
        }
        __syncthreads();

        // stage7: wpre += (r*h) @ Ww_h ; h = h + z*(tanh(wpre) - h)
        gemmT(wacc, swk, 64, rbase, sWw + 68 * 64, 64, c0);
#pragma unroll
        for (int r = 0; r < 7; ++r) {
            int row = rbase + r;
            if (row < NV) {
                float o0, o1, o2, o3;
                upk2(o0, o1, wacc[r][0]); upk2(o2, o3, wacc[r][1]);
                float* hp = sh + row * 64 + c0;
                float4 hv = *reinterpret_cast<const float4*>(hp);
                float n0 = hv.x + zf[r][0] * (tanhf(o0) - hv.x);
                float n1 = hv.y + zf[r][1] * (tanhf(o1) - hv.y);
                float n2 = hv.z + zf[r][2] * (tanhf(o2) - hv.z);
                float n3 = hv.w + zf[r][3] * (tanhf(o3) - hv.w);
                *reinterpret_cast<float4*>(hp) = make_float4(n0, n1, n2, n3);
            }
        }
        // top-of-loop barriers order h writes vs next reads
    }

    __syncthreads();
    for (int i = tid; i < NV * ND; i += 256)
        g_h[(size_t)b * (NV * ND) + i] = sh[i];
}

// ---------------- FC1: g_y = relu(g_h @ Wf1 + bf1), M=8192 K=6464 N=128 ----
__global__ __launch_bounds__(256, 2)
void fc1_kernel(const float* __restrict__ Wf1, const float* __restrict__ bf1)
{
    __shared__ float sA[64 * 16];
    __shared__ float sB[16 * 128];
    const int tid = threadIdx.x;
    const int m0  = blockIdx.x * 64;
    const int tn  = tid & 31;   // 0..31 -> 4 cols each
    const int tm  = tid >> 5;   // 0..7  -> 8 rows each

    float acc[8][4];
#pragma unroll
    for (int i = 0; i < 8; ++i)
#pragma unroll
        for (int j = 0; j < 4; ++j) acc[i][j] = 0.0f;

    const int ai = tid >> 2, ak = (tid & 3) * 4;
    const int bk = tid >> 4, bn = (tid & 15) * 8;

    for (int k0 = 0; k0 < NV * ND; k0 += 16) {
        *reinterpret_cast<float4*>(&sA[ai * 16 + ak]) =
            *reinterpret_cast<const float4*>(&g_h[(size_t)(m0 + ai) * (NV * ND) + k0 + ak]);
        *reinterpret_cast<float4*>(&sB[bk * 128 + bn]) =
            *reinterpret_cast<const float4*>(&Wf1[(size_t)(k0 + bk) * 128 + bn]);
        *reinterpret_cast<float4*>(&sB[bk * 128 + bn + 4]) =
            *reinterpret_cast<const float4*>(&Wf1[(size_t)(k0 + bk) * 128 + bn + 4]);
        __syncthreads();
#pragma unroll
        for (int kk = 0; kk < 16; ++kk) {
            float bv[4];
            *reinterpret_cast<float4*>(bv) =
                *reinterpret_cast<const float4*>(&sB[kk * 128 + tn * 4]);
#pragma unroll
            for (int i = 0; i < 8; ++i) {
                float av = sA[(tm * 8 + i) * 16 + kk];
                acc[i][0] = fmaf(av, bv[0], acc[i][0]);
                acc[i][1] = fmaf(av, bv[1], acc[i][1]);
                acc[i][2] = fmaf(av, bv[2], acc[i][2]);
                acc[i][3] = fmaf(av, bv[3], acc[i][3]);
            }
        }
        __syncthreads();
    }
#pragma unroll
    for (int i = 0; i < 8; ++i) {
        int m = m0 + tm * 8 + i;
#pragma unroll
        for (int j = 0; j < 4; ++j) {
            int n = tn * 4 + j;
            g_y[(size_t)m * 128 + n] = fmaxf(acc[i][j] + bf1[n], 0.0f);
        }
    }
}

// ---------------- head: out = softmax(g_y @ Wf2 + bf2) ----------------
__global__ __launch_bounds__(128)
void head_kernel(const float* __restrict__ Wf2, const float* __restrict__ bf2,
                 float* __restrict__ out)
{
    const int b = blockIdx.x, tid = threadIdx.x;
    __shared__ float sy[128];
    __shared__ float red[128];

    sy[tid] = g_y[(size_t)b * 128 + tid];
    __syncthreads();

    float logit = -3.0e38f;
    if (tid < NV) {
        float s = bf2[tid];
#pragma unroll 4
        for (int k = 0; k < 128; ++k) s = fmaf(sy[k], Wf2[k * NV + tid], s);
        logit = s;
    }
    red[tid] = logit;
    __syncthreads();
#pragma unroll
    for (int off = 64; off > 0; off >>= 1) {
        if (tid < off) red[tid] = fmaxf(red[tid], red[tid + off]);
        __syncthreads();
    }
    float m = red[0];
    __syncthreads();
    float e = (tid < NV) ? expf(logit - m) : 0.0f;
    red[tid] = e;
    __syncthreads();
#pragma unroll
    for (int off = 64; off > 0; off >>= 1) {
        if (tid < off) red[tid] += red[tid + off];
        __syncthreads();
    }
    float s = red[0];
    if (tid < NV) out[(size_t)b * NV + tid] = e / s;
}

extern "C" void kernel_launch(void* const* d_in, const int* in_sizes, int n_in,
                              void* d_out, int out_size)
{
    (void)in_sizes; (void)n_in; (void)out_size;
    const float* x   = (const float*)d_in[0];
    const float* dyn = (const float*)d_in[1];
    const float* W1  = (const float*)d_in[2];
    const float* b1  = (const float*)d_in[3];
    const float* W2  = (const float*)d_in[4];
    const float* b2  = (const float*)d_in[5];
    const float* Wz  = (const float*)d_in[6];
    const float* bz  = (const float*)d_in[7];
    const float* Wr  = (const float*)d_in[8];
    const float* br  = (const float*)d_in[9];
    const float* Ww  = (const float*)d_in[10];
    const float* bw  = (const float*)d_in[11];
    const float* Wf1 = (const float*)d_in[12];
    const float* bf1 = (const float*)d_in[13];
    const float* Wf2 = (const float*)d_in[14];
    const float* bf2 = (const float*)d_in[15];
    float* out = (float*)d_out;

    cudaFuncSetAttribute(mgcgru_scan, cudaFuncAttributeMaxDynamicSharedMemorySize, SMEM_BYTES);
    mgcgru_scan<<<NB, 256, SMEM_BYTES>>>(x, dyn, W1, b1, W2, b2, Wz, bz, Wr, br, Ww, bw);
    fc1_kernel<<<NB / 64, 256>>>(Wf1, bf1);
    head_kernel<<<NB, 128>>>(Wf2, bf2, out);
}